// round 6
// baseline (speedup 1.0000x reference)
#include <cuda_runtime.h>
#include <cuda_bf16.h>

#define N_NODES 50000
#define N_EDGES 800000
#define LATDIM  128

typedef unsigned long long ull;

// ---- scratch (static device globals: the sanctioned no-alloc workaround) ----
__device__ float g_Q[N_NODES * LATDIM];
__device__ float g_K[N_NODES * LATDIM];
__device__ float g_V[N_NODES * LATDIM];
__device__ int   g_cnt[N_NODES];          // zero-init; re-zeroed by pass3 each run
__device__ int   g_excl[N_NODES];
__device__ int   g_bsum[64];
__device__ int   g_boff[64];              // g_boff[63] = grand total
__device__ int   g_rowptr[N_NODES + 1];
__device__ int   g_fill[N_NODES];
__device__ int   g_adj[N_EDGES];

// ---- packed f32x2 helpers (FFMA2 path, sm_103a) ----
__device__ __forceinline__ ull pack2(float lo, float hi) {
    ull r;
    asm("mov.b64 %0, {%1, %2};" : "=l"(r)
        : "r"(__float_as_uint(lo)), "r"(__float_as_uint(hi)));
    return r;
}
__device__ __forceinline__ void fma2(ull& d, ull a, ull b) {
    asm("fma.rn.f32x2 %0, %1, %2, %3;" : "=l"(d) : "l"(a), "l"(b), "l"(d));
}
__device__ __forceinline__ void unpack2(ull v, float& lo, float& hi) {
    unsigned ulo, uhi;
    asm("mov.b64 {%0, %1}, %2;" : "=r"(ulo), "=r"(uhi) : "l"(v));
    lo = __uint_as_float(ulo);
    hi = __uint_as_float(uhi);
}

// ============================================================
// Kernel 1: fused Q/K/V projection + edge histogram.
// grid = (ceil(N/128), 4): y<3 = GEMM slices, y==3 = histogram.
// GEMM: A stored in smem PRE-DUPLICATED as f32x2 pairs (kills the
// 16 MOVs/thread/k of runtime pack2). XOR swizzle on the row index
// (pos = r ^ ((k>>2 & 7)<<1)) breaks the 8-way STS bank conflict the
// dup layout would otherwise have; reads stay LDS.128-vectorizable
// because q2 is even so position pairs map to consecutive rows.
// ============================================================
__global__ __launch_bounds__(256, 2)
void gemm3_hist_kernel(const float* __restrict__ E,
                       const float* __restrict__ qW,
                       const float* __restrict__ kW,
                       const float* __restrict__ vW,
                       const int* __restrict__ rows,
                       int N, int nE)
{
    // --- histogram slice (runs in GEMM's tail wave) ---
    if (blockIdx.y == 3) {
        int stride = gridDim.x * blockDim.x;
        for (int e = blockIdx.x * blockDim.x + threadIdx.x; e < nE; e += stride)
            atomicAdd(&g_cnt[rows[e]], 1);
        return;
    }

    __shared__ ull   As2[32][128];   // A duplicated: As2[k][r^swz] = {a,a}  (32KB)
    __shared__ float Bs[32][128];    // W tile: Bs[k][col]                    (16KB)

    const float* W   = (blockIdx.y == 0) ? qW : (blockIdx.y == 1 ? kW : vW);
    float*       Out = (blockIdx.y == 0) ? g_Q : (blockIdx.y == 1 ? g_K : g_V);

    const int row0 = blockIdx.x * 128;
    const int tid  = threadIdx.x;
    const int tr   = (tid >> 4) << 3;   // thread row base (0..120)
    const int tc   = (tid & 15) << 2;   // col blocks [tc,tc+4) and [tc+64,tc+68)

    ull acc[8][4];
#pragma unroll
    for (int i = 0; i < 8; i++)
#pragma unroll
        for (int j = 0; j < 4; j++) acc[i][j] = 0ULL;

    for (int kc = 0; kc < LATDIM; kc += 32) {
        // load W chunk (32 x 128) into Bs
#pragma unroll
        for (int v = tid; v < 32 * 32; v += 256) {
            int k = v >> 5, c4 = v & 31;
            *(float4*)&Bs[k][c4 * 4] =
                __ldg((const float4*)(W + (size_t)(kc + k) * LATDIM) + c4);
        }
        // load A chunk (128 rows x 32 k), transposed + duplicated + swizzled
        {
            int kq = (tid & 7) * 4;                       // k base (0..28)
            int rb = tid >> 3;                            // row base (0..31)
            int q2 = ((kq >> 2) & 7) << 1;                // swizzle (const per thread)
#pragma unroll
            for (int rr = 0; rr < 4; rr++) {
                int r = rb + rr * 32;
                int grow = row0 + r;
                float4 a = (grow < N)
                    ? __ldg((const float4*)(E + (size_t)grow * LATDIM + kc + kq))
                    : make_float4(0.f, 0.f, 0.f, 0.f);
                int pos = r ^ q2;
                As2[kq + 0][pos] = pack2(a.x, a.x);
                As2[kq + 1][pos] = pack2(a.y, a.y);
                As2[kq + 2][pos] = pack2(a.z, a.z);
                As2[kq + 3][pos] = pack2(a.w, a.w);
            }
        }
        __syncthreads();

#pragma unroll 8
        for (int k = 0; k < 32; k++) {
            int q2 = ((k >> 2) & 7) << 1;
            const ull* Ak = As2[k];
            // position (tr+2m)^q2 holds rows (tr+2m, tr+2m+1)
            ulonglong2 A0 = *(const ulonglong2*)&Ak[(tr + 0) ^ q2];
            ulonglong2 A1 = *(const ulonglong2*)&Ak[(tr + 2) ^ q2];
            ulonglong2 A2 = *(const ulonglong2*)&Ak[(tr + 4) ^ q2];
            ulonglong2 A3 = *(const ulonglong2*)&Ak[(tr + 6) ^ q2];
            ulonglong2 bq0 = *(const ulonglong2*)&Bs[k][tc];        // contiguous
            ulonglong2 bq1 = *(const ulonglong2*)&Bs[k][tc + 64];   // contiguous
            ull bb[4] = {bq0.x, bq0.y, bq1.x, bq1.y};
            ull aa[8] = {A0.x, A0.y, A1.x, A1.y, A2.x, A2.y, A3.x, A3.y};
#pragma unroll
            for (int i = 0; i < 8; i++) {
                fma2(acc[i][0], aa[i], bb[0]);
                fma2(acc[i][1], aa[i], bb[1]);
                fma2(acc[i][2], aa[i], bb[2]);
                fma2(acc[i][3], aa[i], bb[3]);
            }
        }
        __syncthreads();
    }

#pragma unroll
    for (int i = 0; i < 8; i++) {
        int grow = row0 + tr + i;
        if (grow < N) {
            float o[8];
#pragma unroll
            for (int j = 0; j < 4; j++) unpack2(acc[i][j], o[2 * j], o[2 * j + 1]);
            *(float4*)(Out + (size_t)grow * LATDIM + tc)      = make_float4(o[0], o[1], o[2], o[3]);
            *(float4*)(Out + (size_t)grow * LATDIM + tc + 64) = make_float4(o[4], o[5], o[6], o[7]);
        }
    }
}

// ============================================================
// CSR build: (hist fused above) -> 3-pass coalesced scan -> scatter
// ============================================================

// pass 1: per-block coalesced inclusive scan; write per-elem exclusive + block sum
__global__ __launch_bounds__(1024)
void scan_pass1(int n) {
    __shared__ int warp_sums[32];
    const int tid  = threadIdx.x;
    const int lane = tid & 31;
    const int wid  = tid >> 5;
    const int i    = blockIdx.x * 1024 + tid;

    int v = (i < n) ? g_cnt[i] : 0;

    int s = v;
#pragma unroll
    for (int o = 1; o < 32; o <<= 1) {
        int t = __shfl_up_sync(0xffffffffu, s, o);
        if (lane >= o) s += t;
    }
    if (lane == 31) warp_sums[wid] = s;
    __syncthreads();

    if (wid == 0) {
        int w = warp_sums[lane];
#pragma unroll
        for (int o = 1; o < 32; o <<= 1) {
            int t = __shfl_up_sync(0xffffffffu, w, o);
            if (lane >= o) w += t;
        }
        warp_sums[lane] = w;
    }
    __syncthreads();

    int incl = s + (wid > 0 ? warp_sums[wid - 1] : 0);
    if (i < n) g_excl[i] = incl - v;
    if (tid == 1023) g_bsum[blockIdx.x] = incl;
}

// pass 2: one warp scans the (<=63) block sums -> exclusive offsets + total
__global__ void scan_pass2(int nb) {
    int lane = threadIdx.x;                 // 32 threads
    int a0 = (lane < nb)      ? g_bsum[lane]      : 0;
    int b0 = (lane + 32 < nb) ? g_bsum[lane + 32] : 0;
    int a = a0, b = b0;
#pragma unroll
    for (int o = 1; o < 32; o <<= 1) {
        int t = __shfl_up_sync(0xffffffffu, a, o);
        if (lane >= o) a += t;
    }
    int lowTot = __shfl_sync(0xffffffffu, a, 31);
#pragma unroll
    for (int o = 1; o < 32; o <<= 1) {
        int t = __shfl_up_sync(0xffffffffu, b, o);
        if (lane >= o) b += t;
    }
    b += lowTot;
    g_boff[lane] = a - a0;
    if (lane + 32 < 63) g_boff[lane + 32] = b - b0;
    if (lane == 31) g_boff[63] = __shfl_sync(0xffffffffu, b, 31);
}

// pass 3: add block offsets, materialize rowptr/fill + sentinel.
// Also re-zeros g_cnt (already consumed by pass1) so next replay's
// fused histogram starts from zeros — keeps every call's work identical.
__global__ __launch_bounds__(1024)
void scan_pass3(int n) {
    int i = blockIdx.x * 1024 + threadIdx.x;
    if (i < n) {
        int r = g_excl[i] + g_boff[i >> 10];
        g_rowptr[i] = r;
        g_fill[i]   = r;
        g_cnt[i]    = 0;
    } else if (i == n) {
        g_rowptr[n] = g_boff[63];
    }
}

__global__ void scatter_kernel(const int* __restrict__ rows,
                               const int* __restrict__ cols, int nE) {
    int e = blockIdx.x * blockDim.x + threadIdx.x;
    if (e < nE) {
        int r = rows[e];
        int pos = atomicAdd(&g_fill[r], 1);
        g_adj[pos] = cols[e];
    }
}

// ============================================================
// Kernel 2: fused per-node attention. One warp per node.
// lane l owns dims [4l, 4l+4); head = l/8; 8-lane shfl reduce per head.
// 2-edge unroll: 4 independent LDG.128 in flight per iteration.
// out[n] = (sum_e exp(clip(q.k)) * v) / (sum_e exp + 1e-8)
// ============================================================
__global__ void attn_kernel(float* __restrict__ out, int N) {
    int warp = (blockIdx.x * blockDim.x + threadIdx.x) >> 5;
    int lane = threadIdx.x & 31;
    if (warp >= N) return;

    const float4 q = __ldg((const float4*)(g_Q + (size_t)warp * LATDIM) + lane);
    int beg = g_rowptr[warp];
    int end = g_rowptr[warp + 1];

    float ax = 0.f, ay = 0.f, az = 0.f, aw = 0.f, denom = 0.f;

    int i = beg;
    for (; i + 2 <= end; i += 2) {
        int c0 = __ldg(g_adj + i);
        int c1 = __ldg(g_adj + i + 1);
        const float4 k0 = __ldg((const float4*)(g_K + (size_t)c0 * LATDIM) + lane);
        const float4 v0 = __ldg((const float4*)(g_V + (size_t)c0 * LATDIM) + lane);
        const float4 k1 = __ldg((const float4*)(g_K + (size_t)c1 * LATDIM) + lane);
        const float4 v1 = __ldg((const float4*)(g_V + (size_t)c1 * LATDIM) + lane);

        float p0 = q.x * k0.x + q.y * k0.y + q.z * k0.z + q.w * k0.w;
        float p1 = q.x * k1.x + q.y * k1.y + q.z * k1.z + q.w * k1.w;
        p0 += __shfl_xor_sync(0xffffffffu, p0, 1);
        p1 += __shfl_xor_sync(0xffffffffu, p1, 1);
        p0 += __shfl_xor_sync(0xffffffffu, p0, 2);
        p1 += __shfl_xor_sync(0xffffffffu, p1, 2);
        p0 += __shfl_xor_sync(0xffffffffu, p0, 4);
        p1 += __shfl_xor_sync(0xffffffffu, p1, 4);
        p0 = fminf(fmaxf(p0, -10.f), 10.f);
        p1 = fminf(fmaxf(p1, -10.f), 10.f);
        float e0 = __expf(p0);
        float e1 = __expf(p1);
        denom += e0 + e1;
        ax = fmaf(e0, v0.x, ax); ax = fmaf(e1, v1.x, ax);
        ay = fmaf(e0, v0.y, ay); ay = fmaf(e1, v1.y, ay);
        az = fmaf(e0, v0.z, az); az = fmaf(e1, v1.z, az);
        aw = fmaf(e0, v0.w, aw); aw = fmaf(e1, v1.w, aw);
    }
    if (i < end) {
        int c = __ldg(g_adj + i);
        const float4 k4 = __ldg((const float4*)(g_K + (size_t)c * LATDIM) + lane);
        const float4 v4 = __ldg((const float4*)(g_V + (size_t)c * LATDIM) + lane);
        float p = q.x * k4.x + q.y * k4.y + q.z * k4.z + q.w * k4.w;
        p += __shfl_xor_sync(0xffffffffu, p, 1);
        p += __shfl_xor_sync(0xffffffffu, p, 2);
        p += __shfl_xor_sync(0xffffffffu, p, 4);
        p = fminf(fmaxf(p, -10.f), 10.f);
        float e = __expf(p);
        denom += e;
        ax = fmaf(e, v4.x, ax);
        ay = fmaf(e, v4.y, ay);
        az = fmaf(e, v4.z, az);
        aw = fmaf(e, v4.w, aw);
    }

    float inv = 1.f / (denom + 1e-8f);
    float4 o = make_float4(ax * inv, ay * inv, az * inv, aw * inv);
    *((float4*)out + (size_t)warp * 32 + lane) = o;
}

// ============================================================
extern "C" void kernel_launch(void* const* d_in, const int* in_sizes, int n_in,
                              void* d_out, int out_size) {
    const float* E    = (const float*)d_in[0];
    const float* qW   = (const float*)d_in[1];
    const float* kW   = (const float*)d_in[2];
    const float* vW   = (const float*)d_in[3];
    const int*   rows = (const int*)d_in[4];
    const int*   cols = (const int*)d_in[5];

    int N  = in_sizes[0] / LATDIM;
    int Eg = in_sizes[4];

    int nb = (N + 1023) / 1024;

    // GEMM (y<3) + histogram (y==3) in one launch; hist blocks are scheduled
    // last and fill the GEMM tail wave. g_cnt is zero on entry (static init /
    // re-zeroed by scan_pass3 each run).
    dim3 gg((N + 127) / 128, 4);
    gemm3_hist_kernel<<<gg, 256>>>(E, qW, kW, vW, rows, N, Eg);

    scan_pass1<<<nb, 1024>>>(N);
    scan_pass2<<<1, 32>>>(nb);
    scan_pass3<<<(N + 1024) / 1024, 1024>>>(N);   // covers i == N sentinel
    scatter_kernel<<<(Eg + 255) / 256, 256>>>(rows, cols, Eg);

    attn_kernel<<<(N + 7) / 8, 256>>>((float*)d_out, N);
}

// round 7
// speedup vs baseline: 1.1257x; 1.1257x over previous
#include <cuda_runtime.h>
#include <cuda_bf16.h>

#define N_NODES 50000
#define N_EDGES 800000
#define LATDIM  128

typedef unsigned long long ull;

// ---- scratch (static device globals: the sanctioned no-alloc workaround) ----
__device__ float g_Q[N_NODES * LATDIM];
__device__ float g_K[N_NODES * LATDIM];
__device__ float g_V[N_NODES * LATDIM];
__device__ int   g_cnt[N_NODES];          // zero-init; re-zeroed by pass3 each run
__device__ int   g_excl[N_NODES];
__device__ int   g_bsum[64];
__device__ int   g_boff[64];              // g_boff[63] = grand total
__device__ int   g_rowptr[N_NODES + 1];
__device__ int   g_fill[N_NODES];
__device__ int   g_adj[N_EDGES];

// ---- packed f32x2 helpers (FFMA2 path, sm_103a) ----
__device__ __forceinline__ ull pack2(float lo, float hi) {
    ull r;
    asm("mov.b64 %0, {%1, %2};" : "=l"(r)
        : "r"(__float_as_uint(lo)), "r"(__float_as_uint(hi)));
    return r;
}
__device__ __forceinline__ void fma2(ull& d, ull a, ull b) {
    asm("fma.rn.f32x2 %0, %1, %2, %3;" : "=l"(d) : "l"(a), "l"(b), "l"(d));
}
__device__ __forceinline__ void unpack2(ull v, float& lo, float& hi) {
    unsigned ulo, uhi;
    asm("mov.b64 {%0, %1}, %2;" : "=r"(ulo), "=r"(uhi) : "l"(v));
    lo = __uint_as_float(ulo);
    hi = __uint_as_float(uhi);
}

// ============================================================
// Kernel 1: fused Q/K/V projection (R5 mainloop: minimal smem bytes)
// + edge histogram. grid = (ceil(N/128), 4): y<3 GEMM, y==3 hist.
// GEMM per thread: 8 rows x (4+4) cols, runtime pack2 of A (the MOVs
// are cheaper than doubling A's smem-crossbar bytes — measured R6).
// ============================================================
__global__ __launch_bounds__(256, 2)
void gemm3_hist_kernel(const float* __restrict__ E,
                       const float* __restrict__ qW,
                       const float* __restrict__ kW,
                       const float* __restrict__ vW,
                       const int* __restrict__ rows,
                       int N, int nE)
{
    // --- histogram slice: blockIdx.y==3 blocks are scheduled after all
    // GEMM blocks (y-major linearization) and fill the GEMM tail wave ---
    if (blockIdx.y == 3) {
        int stride = gridDim.x * blockDim.x;
        for (int e = blockIdx.x * blockDim.x + threadIdx.x; e < nE; e += stride)
            atomicAdd(&g_cnt[rows[e]], 1);
        return;
    }

    __shared__ float As[32][132];   // A tile transposed: As[k][row]
    __shared__ float Bs[32][128];   // W tile: Bs[k][col]

    const float* W   = (blockIdx.y == 0) ? qW : (blockIdx.y == 1 ? kW : vW);
    float*       Out = (blockIdx.y == 0) ? g_Q : (blockIdx.y == 1 ? g_K : g_V);

    const int row0 = blockIdx.x * 128;
    const int tid  = threadIdx.x;
    const int tr   = (tid >> 4) << 3;   // thread row base (0..120)
    const int tc   = (tid & 15) << 2;   // col blocks [tc,tc+4) and [tc+64,tc+68)

    ull acc[8][4];
#pragma unroll
    for (int i = 0; i < 8; i++)
#pragma unroll
        for (int j = 0; j < 4; j++) acc[i][j] = 0ULL;

    for (int kc = 0; kc < LATDIM; kc += 32) {
        // load W chunk (32 x 128) into Bs
#pragma unroll
        for (int v = tid; v < 32 * 32; v += 256) {
            int k = v >> 5, c4 = v & 31;
            *(float4*)&Bs[k][c4 * 4] =
                __ldg((const float4*)(W + (size_t)(kc + k) * LATDIM) + c4);
        }
        // load A chunk (128 rows x 32 k) transposed into As
        {
            int kq = (tid & 7) * 4;
            int rb = tid >> 3;
#pragma unroll
            for (int rr = 0; rr < 4; rr++) {
                int r = rb + rr * 32;
                int grow = row0 + r;
                float4 a = (grow < N)
                    ? __ldg((const float4*)(E + (size_t)grow * LATDIM + kc + kq))
                    : make_float4(0.f, 0.f, 0.f, 0.f);
                As[kq + 0][r] = a.x;
                As[kq + 1][r] = a.y;
                As[kq + 2][r] = a.z;
                As[kq + 3][r] = a.w;
            }
        }
        __syncthreads();

#pragma unroll 8
        for (int k = 0; k < 32; k++) {
            float4 a0 = *(const float4*)&As[k][tr];        // broadcast
            float4 a1 = *(const float4*)&As[k][tr + 4];    // broadcast
            ulonglong2 bq0 = *(const ulonglong2*)&Bs[k][tc];       // contiguous
            ulonglong2 bq1 = *(const ulonglong2*)&Bs[k][tc + 64];  // contiguous
            ull bb[4] = {bq0.x, bq0.y, bq1.x, bq1.y};
            ull aa[8];
            aa[0] = pack2(a0.x, a0.x); aa[1] = pack2(a0.y, a0.y);
            aa[2] = pack2(a0.z, a0.z); aa[3] = pack2(a0.w, a0.w);
            aa[4] = pack2(a1.x, a1.x); aa[5] = pack2(a1.y, a1.y);
            aa[6] = pack2(a1.z, a1.z); aa[7] = pack2(a1.w, a1.w);
#pragma unroll
            for (int i = 0; i < 8; i++) {
                fma2(acc[i][0], aa[i], bb[0]);
                fma2(acc[i][1], aa[i], bb[1]);
                fma2(acc[i][2], aa[i], bb[2]);
                fma2(acc[i][3], aa[i], bb[3]);
            }
        }
        __syncthreads();
    }

#pragma unroll
    for (int i = 0; i < 8; i++) {
        int grow = row0 + tr + i;
        if (grow < N) {
            float o[8];
#pragma unroll
            for (int j = 0; j < 4; j++) unpack2(acc[i][j], o[2 * j], o[2 * j + 1]);
            *(float4*)(Out + (size_t)grow * LATDIM + tc)      = make_float4(o[0], o[1], o[2], o[3]);
            *(float4*)(Out + (size_t)grow * LATDIM + tc + 64) = make_float4(o[4], o[5], o[6], o[7]);
        }
    }
}

// ============================================================
// CSR build: (hist fused above) -> 3-pass coalesced scan -> scatter
// ============================================================

// pass 1: per-block coalesced inclusive scan; write per-elem exclusive + block sum
__global__ __launch_bounds__(1024)
void scan_pass1(int n) {
    __shared__ int warp_sums[32];
    const int tid  = threadIdx.x;
    const int lane = tid & 31;
    const int wid  = tid >> 5;
    const int i    = blockIdx.x * 1024 + tid;

    int v = (i < n) ? g_cnt[i] : 0;

    int s = v;
#pragma unroll
    for (int o = 1; o < 32; o <<= 1) {
        int t = __shfl_up_sync(0xffffffffu, s, o);
        if (lane >= o) s += t;
    }
    if (lane == 31) warp_sums[wid] = s;
    __syncthreads();

    if (wid == 0) {
        int w = warp_sums[lane];
#pragma unroll
        for (int o = 1; o < 32; o <<= 1) {
            int t = __shfl_up_sync(0xffffffffu, w, o);
            if (lane >= o) w += t;
        }
        warp_sums[lane] = w;
    }
    __syncthreads();

    int incl = s + (wid > 0 ? warp_sums[wid - 1] : 0);
    if (i < n) g_excl[i] = incl - v;
    if (tid == 1023) g_bsum[blockIdx.x] = incl;
}

// pass 2: one warp scans the (<=63) block sums -> exclusive offsets + total
__global__ void scan_pass2(int nb) {
    int lane = threadIdx.x;                 // 32 threads
    int a0 = (lane < nb)      ? g_bsum[lane]      : 0;
    int b0 = (lane + 32 < nb) ? g_bsum[lane + 32] : 0;
    int a = a0, b = b0;
#pragma unroll
    for (int o = 1; o < 32; o <<= 1) {
        int t = __shfl_up_sync(0xffffffffu, a, o);
        if (lane >= o) a += t;
    }
    int lowTot = __shfl_sync(0xffffffffu, a, 31);
#pragma unroll
    for (int o = 1; o < 32; o <<= 1) {
        int t = __shfl_up_sync(0xffffffffu, b, o);
        if (lane >= o) b += t;
    }
    b += lowTot;
    g_boff[lane] = a - a0;
    if (lane + 32 < 63) g_boff[lane + 32] = b - b0;
    if (lane == 31) g_boff[63] = __shfl_sync(0xffffffffu, b, 31);
}

// pass 3: add block offsets, materialize rowptr/fill + sentinel.
// Re-zeros g_cnt (already consumed by pass1) so the next call's fused
// histogram starts from zeros — every call does identical work.
__global__ __launch_bounds__(1024)
void scan_pass3(int n) {
    int i = blockIdx.x * 1024 + threadIdx.x;
    if (i < n) {
        int r = g_excl[i] + g_boff[i >> 10];
        g_rowptr[i] = r;
        g_fill[i]   = r;
        g_cnt[i]    = 0;
    } else if (i == n) {
        g_rowptr[n] = g_boff[63];
    }
}

__global__ void scatter_kernel(const int* __restrict__ rows,
                               const int* __restrict__ cols, int nE) {
    int e = blockIdx.x * blockDim.x + threadIdx.x;
    if (e < nE) {
        int r = rows[e];
        int pos = atomicAdd(&g_fill[r], 1);
        g_adj[pos] = cols[e];
    }
}

// ============================================================
// Kernel 2: fused per-node attention. One warp per node.
// lane l owns dims [4l, 4l+4); head = l/8; 8-lane shfl reduce per head.
// 2-edge unroll: 4 independent LDG.128 in flight per iteration.
// out[n] = (sum_e exp(clip(q.k)) * v) / (sum_e exp + 1e-8)
// ============================================================
__global__ void attn_kernel(float* __restrict__ out, int N) {
    int warp = (blockIdx.x * blockDim.x + threadIdx.x) >> 5;
    int lane = threadIdx.x & 31;
    if (warp >= N) return;

    const float4 q = __ldg((const float4*)(g_Q + (size_t)warp * LATDIM) + lane);
    int beg = g_rowptr[warp];
    int end = g_rowptr[warp + 1];

    float ax = 0.f, ay = 0.f, az = 0.f, aw = 0.f, denom = 0.f;

    int i = beg;
    for (; i + 2 <= end; i += 2) {
        int c0 = __ldg(g_adj + i);
        int c1 = __ldg(g_adj + i + 1);
        const float4 k0 = __ldg((const float4*)(g_K + (size_t)c0 * LATDIM) + lane);
        const float4 v0 = __ldg((const float4*)(g_V + (size_t)c0 * LATDIM) + lane);
        const float4 k1 = __ldg((const float4*)(g_K + (size_t)c1 * LATDIM) + lane);
        const float4 v1 = __ldg((const float4*)(g_V + (size_t)c1 * LATDIM) + lane);

        float p0 = q.x * k0.x + q.y * k0.y + q.z * k0.z + q.w * k0.w;
        float p1 = q.x * k1.x + q.y * k1.y + q.z * k1.z + q.w * k1.w;
        p0 += __shfl_xor_sync(0xffffffffu, p0, 1);
        p1 += __shfl_xor_sync(0xffffffffu, p1, 1);
        p0 += __shfl_xor_sync(0xffffffffu, p0, 2);
        p1 += __shfl_xor_sync(0xffffffffu, p1, 2);
        p0 += __shfl_xor_sync(0xffffffffu, p0, 4);
        p1 += __shfl_xor_sync(0xffffffffu, p1, 4);
        p0 = fminf(fmaxf(p0, -10.f), 10.f);
        p1 = fminf(fmaxf(p1, -10.f), 10.f);
        float e0 = __expf(p0);
        float e1 = __expf(p1);
        denom += e0 + e1;
        ax = fmaf(e0, v0.x, ax); ax = fmaf(e1, v1.x, ax);
        ay = fmaf(e0, v0.y, ay); ay = fmaf(e1, v1.y, ay);
        az = fmaf(e0, v0.z, az); az = fmaf(e1, v1.z, az);
        aw = fmaf(e0, v0.w, aw); aw = fmaf(e1, v1.w, aw);
    }
    if (i < end) {
        int c = __ldg(g_adj + i);
        const float4 k4 = __ldg((const float4*)(g_K + (size_t)c * LATDIM) + lane);
        const float4 v4 = __ldg((const float4*)(g_V + (size_t)c * LATDIM) + lane);
        float p = q.x * k4.x + q.y * k4.y + q.z * k4.z + q.w * k4.w;
        p += __shfl_xor_sync(0xffffffffu, p, 1);
        p += __shfl_xor_sync(0xffffffffu, p, 2);
        p += __shfl_xor_sync(0xffffffffu, p, 4);
        p = fminf(fmaxf(p, -10.f), 10.f);
        float e = __expf(p);
        denom += e;
        ax = fmaf(e, v4.x, ax);
        ay = fmaf(e, v4.y, ay);
        az = fmaf(e, v4.z, az);
        aw = fmaf(e, v4.w, aw);
    }

    float inv = 1.f / (denom + 1e-8f);
    float4 o = make_float4(ax * inv, ay * inv, az * inv, aw * inv);
    *((float4*)out + (size_t)warp * 32 + lane) = o;
}

// ============================================================
extern "C" void kernel_launch(void* const* d_in, const int* in_sizes, int n_in,
                              void* d_out, int out_size) {
    const float* E    = (const float*)d_in[0];
    const float* qW   = (const float*)d_in[1];
    const float* kW   = (const float*)d_in[2];
    const float* vW   = (const float*)d_in[3];
    const int*   rows = (const int*)d_in[4];
    const int*   cols = (const int*)d_in[5];

    int N  = in_sizes[0] / LATDIM;
    int Eg = in_sizes[4];

    int nb = (N + 1023) / 1024;

    // GEMM (y<3) + histogram (y==3) in one launch; hist blocks scheduled
    // last, filling the GEMM tail wave. g_cnt is zero on entry (static init /
    // re-zeroed by scan_pass3 each call).
    dim3 gg((N + 127) / 128, 4);
    gemm3_hist_kernel<<<gg, 256>>>(E, qW, kW, vW, rows, N, Eg);

    scan_pass1<<<nb, 1024>>>(N);
    scan_pass2<<<1, 32>>>(nb);
    scan_pass3<<<(N + 1024) / 1024, 1024>>>(N);   // covers i == N sentinel
    scatter_kernel<<<(Eg + 255) / 256, 256>>>(rows, cols, Eg);

    attn_kernel<<<(N + 7) / 8, 256>>>((float*)d_out, N);
}

// round 8
// speedup vs baseline: 1.1508x; 1.0223x over previous
#include <cuda_runtime.h>
#include <cuda_bf16.h>

#define N_NODES 50000
#define N_EDGES 800000
#define LATDIM  128

typedef unsigned long long ull;

// ---- scratch (static device globals: the sanctioned no-alloc workaround) ----
__device__ float g_Q[N_NODES * LATDIM];
__device__ float g_K[N_NODES * LATDIM];
__device__ float g_V[N_NODES * LATDIM];
__device__ int   g_cnt[N_NODES];       // zero-init; re-zeroed by scan each run
__device__ int   g_bsum[64];           // lookback slots: 0 = unpublished, else total+1
                                       // (zero-init; reset to 0 by scatter each run)
__device__ int   g_rowptr[N_NODES + 1];
__device__ int   g_fill[N_NODES];
__device__ int   g_adj[N_EDGES];

// ---- packed f32x2 helpers (FFMA2 path, sm_103a) ----
__device__ __forceinline__ ull pack2(float lo, float hi) {
    ull r;
    asm("mov.b64 %0, {%1, %2};" : "=l"(r)
        : "r"(__float_as_uint(lo)), "r"(__float_as_uint(hi)));
    return r;
}
__device__ __forceinline__ void fma2(ull& d, ull a, ull b) {
    asm("fma.rn.f32x2 %0, %1, %2, %3;" : "=l"(d) : "l"(a), "l"(b), "l"(d));
}
__device__ __forceinline__ void unpack2(ull v, float& lo, float& hi) {
    unsigned ulo, uhi;
    asm("mov.b64 {%0, %1}, %2;" : "=r"(ulo), "=r"(uhi) : "l"(v));
    lo = __uint_as_float(ulo);
    hi = __uint_as_float(uhi);
}

// ============================================================
// Kernel 1: fused Q/K/V projection (R5 mainloop: minimal smem bytes)
// + edge histogram. grid = (ceil(N/128), 4): y<3 GEMM, y==3 hist.
// ============================================================
__global__ __launch_bounds__(256, 2)
void gemm3_hist_kernel(const float* __restrict__ E,
                       const float* __restrict__ qW,
                       const float* __restrict__ kW,
                       const float* __restrict__ vW,
                       const int* __restrict__ rows,
                       int N, int nE)
{
    // --- histogram slice: scheduled after GEMM blocks, fills the tail wave ---
    if (blockIdx.y == 3) {
        int stride = gridDim.x * blockDim.x;
        for (int e = blockIdx.x * blockDim.x + threadIdx.x; e < nE; e += stride)
            atomicAdd(&g_cnt[rows[e]], 1);
        return;
    }

    __shared__ float As[32][132];   // A tile transposed: As[k][row]
    __shared__ float Bs[32][128];   // W tile: Bs[k][col]

    const float* W   = (blockIdx.y == 0) ? qW : (blockIdx.y == 1 ? kW : vW);
    float*       Out = (blockIdx.y == 0) ? g_Q : (blockIdx.y == 1 ? g_K : g_V);

    const int row0 = blockIdx.x * 128;
    const int tid  = threadIdx.x;
    const int tr   = (tid >> 4) << 3;   // thread row base (0..120)
    const int tc   = (tid & 15) << 2;   // col blocks [tc,tc+4) and [tc+64,tc+68)

    ull acc[8][4];
#pragma unroll
    for (int i = 0; i < 8; i++)
#pragma unroll
        for (int j = 0; j < 4; j++) acc[i][j] = 0ULL;

    for (int kc = 0; kc < LATDIM; kc += 32) {
#pragma unroll
        for (int v = tid; v < 32 * 32; v += 256) {
            int k = v >> 5, c4 = v & 31;
            *(float4*)&Bs[k][c4 * 4] =
                __ldg((const float4*)(W + (size_t)(kc + k) * LATDIM) + c4);
        }
        {
            int kq = (tid & 7) * 4;
            int rb = tid >> 3;
#pragma unroll
            for (int rr = 0; rr < 4; rr++) {
                int r = rb + rr * 32;
                int grow = row0 + r;
                float4 a = (grow < N)
                    ? __ldg((const float4*)(E + (size_t)grow * LATDIM + kc + kq))
                    : make_float4(0.f, 0.f, 0.f, 0.f);
                As[kq + 0][r] = a.x;
                As[kq + 1][r] = a.y;
                As[kq + 2][r] = a.z;
                As[kq + 3][r] = a.w;
            }
        }
        __syncthreads();

#pragma unroll 8
        for (int k = 0; k < 32; k++) {
            float4 a0 = *(const float4*)&As[k][tr];        // broadcast
            float4 a1 = *(const float4*)&As[k][tr + 4];    // broadcast
            ulonglong2 bq0 = *(const ulonglong2*)&Bs[k][tc];       // contiguous
            ulonglong2 bq1 = *(const ulonglong2*)&Bs[k][tc + 64];  // contiguous
            ull bb[4] = {bq0.x, bq0.y, bq1.x, bq1.y};
            ull aa[8];
            aa[0] = pack2(a0.x, a0.x); aa[1] = pack2(a0.y, a0.y);
            aa[2] = pack2(a0.z, a0.z); aa[3] = pack2(a0.w, a0.w);
            aa[4] = pack2(a1.x, a1.x); aa[5] = pack2(a1.y, a1.y);
            aa[6] = pack2(a1.z, a1.z); aa[7] = pack2(a1.w, a1.w);
#pragma unroll
            for (int i = 0; i < 8; i++) {
                fma2(acc[i][0], aa[i], bb[0]);
                fma2(acc[i][1], aa[i], bb[1]);
                fma2(acc[i][2], aa[i], bb[2]);
                fma2(acc[i][3], aa[i], bb[3]);
            }
        }
        __syncthreads();
    }

#pragma unroll
    for (int i = 0; i < 8; i++) {
        int grow = row0 + tr + i;
        if (grow < N) {
            float o[8];
#pragma unroll
            for (int j = 0; j < 4; j++) unpack2(acc[i][j], o[2 * j], o[2 * j + 1]);
            *(float4*)(Out + (size_t)grow * LATDIM + tc)      = make_float4(o[0], o[1], o[2], o[3]);
            *(float4*)(Out + (size_t)grow * LATDIM + tc + 64) = make_float4(o[4], o[5], o[6], o[7]);
        }
    }
}

// ============================================================
// Single-launch exclusive scan with inter-block lookback.
// 49 blocks (all co-resident in wave 1: 49 < 148 SMs, so spin-wait is
// deadlock-free). Each block: local scan -> publish tile_total+1 via
// atomicExch (0 = unpublished, matches static zero-init) -> threads
// tid<bid poll predecessors -> offset -> write rowptr/fill, zero cnt.
// scatter_kernel resets g_bsum to 0 afterwards (launch-ordered), so
// every call does identical work.
// ============================================================
__global__ __launch_bounds__(1024)
void scan_fused(int n) {
    __shared__ int warp_sums[32];
    __shared__ int s_offset;
    const int tid  = threadIdx.x;
    const int lane = tid & 31;
    const int wid  = tid >> 5;
    const int bid  = blockIdx.x;
    const int i    = bid * 1024 + tid;

    int v = (i < n) ? g_cnt[i] : 0;

    // block-local inclusive scan
    int s = v;
#pragma unroll
    for (int o = 1; o < 32; o <<= 1) {
        int t = __shfl_up_sync(0xffffffffu, s, o);
        if (lane >= o) s += t;
    }
    if (lane == 31) warp_sums[wid] = s;
    __syncthreads();
    if (wid == 0) {
        int w = warp_sums[lane];
#pragma unroll
        for (int o = 1; o < 32; o <<= 1) {
            int t = __shfl_up_sync(0xffffffffu, w, o);
            if (lane >= o) w += t;
        }
        warp_sums[lane] = w;
    }
    __syncthreads();
    int incl = s + (wid > 0 ? warp_sums[wid - 1] : 0);

    // publish this block's total (+1 so 0 stays the "unpublished" sentinel)
    if (tid == 1023) atomicExch(&g_bsum[bid], incl + 1);
    if (tid == 0) s_offset = 0;
    __syncthreads();

    // lookback: thread t (< bid) spins on predecessor t's slot
    if (tid < bid) {
        int pv;
        do { pv = atomicAdd(&g_bsum[tid], 0); } while (pv == 0);
        atomicAdd(&s_offset, pv - 1);
    }
    __syncthreads();

    int r = s_offset + incl - v;   // global exclusive prefix
    if (i < n) {
        g_rowptr[i] = r;
        g_fill[i]   = r;
        g_cnt[i]    = 0;           // re-zero for next call's fused histogram
    } else if (i == n) {
        g_rowptr[n] = r;           // v==0 past n, so r == grand total
    }
}

__global__ void scatter_kernel(const int* __restrict__ rows,
                               const int* __restrict__ cols, int nE) {
    int e = blockIdx.x * blockDim.x + threadIdx.x;
    if (e < 64) g_bsum[e] = 0;     // reset lookback slots for next call
    if (e < nE) {
        int r = rows[e];
        int pos = atomicAdd(&g_fill[r], 1);
        g_adj[pos] = cols[e];
    }
}

// ============================================================
// Kernel 2: fused per-node attention. One warp per node.
// 2-edge unroll: 4 independent LDG.128 in flight per iteration.
// ============================================================
__global__ void attn_kernel(float* __restrict__ out, int N) {
    int warp = (blockIdx.x * blockDim.x + threadIdx.x) >> 5;
    int lane = threadIdx.x & 31;
    if (warp >= N) return;

    const float4 q = __ldg((const float4*)(g_Q + (size_t)warp * LATDIM) + lane);
    int beg = g_rowptr[warp];
    int end = g_rowptr[warp + 1];

    float ax = 0.f, ay = 0.f, az = 0.f, aw = 0.f, denom = 0.f;

    int i = beg;
    for (; i + 2 <= end; i += 2) {
        int c0 = __ldg(g_adj + i);
        int c1 = __ldg(g_adj + i + 1);
        const float4 k0 = __ldg((const float4*)(g_K + (size_t)c0 * LATDIM) + lane);
        const float4 v0 = __ldg((const float4*)(g_V + (size_t)c0 * LATDIM) + lane);
        const float4 k1 = __ldg((const float4*)(g_K + (size_t)c1 * LATDIM) + lane);
        const float4 v1 = __ldg((const float4*)(g_V + (size_t)c1 * LATDIM) + lane);

        float p0 = q.x * k0.x + q.y * k0.y + q.z * k0.z + q.w * k0.w;
        float p1 = q.x * k1.x + q.y * k1.y + q.z * k1.z + q.w * k1.w;
        p0 += __shfl_xor_sync(0xffffffffu, p0, 1);
        p1 += __shfl_xor_sync(0xffffffffu, p1, 1);
        p0 += __shfl_xor_sync(0xffffffffu, p0, 2);
        p1 += __shfl_xor_sync(0xffffffffu, p1, 2);
        p0 += __shfl_xor_sync(0xffffffffu, p0, 4);
        p1 += __shfl_xor_sync(0xffffffffu, p1, 4);
        p0 = fminf(fmaxf(p0, -10.f), 10.f);
        p1 = fminf(fmaxf(p1, -10.f), 10.f);
        float e0 = __expf(p0);
        float e1 = __expf(p1);
        denom += e0 + e1;
        ax = fmaf(e0, v0.x, ax); ax = fmaf(e1, v1.x, ax);
        ay = fmaf(e0, v0.y, ay); ay = fmaf(e1, v1.y, ay);
        az = fmaf(e0, v0.z, az); az = fmaf(e1, v1.z, az);
        aw = fmaf(e0, v0.w, aw); aw = fmaf(e1, v1.w, aw);
    }
    if (i < end) {
        int c = __ldg(g_adj + i);
        const float4 k4 = __ldg((const float4*)(g_K + (size_t)c * LATDIM) + lane);
        const float4 v4 = __ldg((const float4*)(g_V + (size_t)c * LATDIM) + lane);
        float p = q.x * k4.x + q.y * k4.y + q.z * k4.z + q.w * k4.w;
        p += __shfl_xor_sync(0xffffffffu, p, 1);
        p += __shfl_xor_sync(0xffffffffu, p, 2);
        p += __shfl_xor_sync(0xffffffffu, p, 4);
        p = fminf(fmaxf(p, -10.f), 10.f);
        float e = __expf(p);
        denom += e;
        ax = fmaf(e, v4.x, ax);
        ay = fmaf(e, v4.y, ay);
        az = fmaf(e, v4.z, az);
        aw = fmaf(e, v4.w, aw);
    }

    float inv = 1.f / (denom + 1e-8f);
    float4 o = make_float4(ax * inv, ay * inv, az * inv, aw * inv);
    *((float4*)out + (size_t)warp * 32 + lane) = o;
}

// ============================================================
extern "C" void kernel_launch(void* const* d_in, const int* in_sizes, int n_in,
                              void* d_out, int out_size) {
    const float* E    = (const float*)d_in[0];
    const float* qW   = (const float*)d_in[1];
    const float* kW   = (const float*)d_in[2];
    const float* vW   = (const float*)d_in[3];
    const int*   rows = (const int*)d_in[4];
    const int*   cols = (const int*)d_in[5];

    int N  = in_sizes[0] / LATDIM;
    int Eg = in_sizes[4];

    int nb = (N + 1023) / 1024;   // 49 blocks — all co-resident (deadlock-free)

    dim3 gg((N + 127) / 128, 4);
    gemm3_hist_kernel<<<gg, 256>>>(E, qW, kW, vW, rows, N, Eg);   // launch 1
    scan_fused<<<nb, 1024>>>(N);                                  // launch 2
    scatter_kernel<<<(Eg + 255) / 256, 256>>>(rows, cols, Eg);    // launch 3
    attn_kernel<<<(N + 7) / 8, 256>>>((float*)d_out, N);          // launch 4 <- ncu slot
}

// round 10
// speedup vs baseline: 1.1643x; 1.0117x over previous
#include <cuda_runtime.h>
#include <cuda_bf16.h>

#define N_NODES 50000
#define N_EDGES 800000
#define LATDIM  128

typedef unsigned long long ull;

// ---- scratch (static device globals: the sanctioned no-alloc workaround) ----
__device__ float g_Q[N_NODES * LATDIM];
__device__ float g_K[N_NODES * LATDIM];
__device__ float g_V[N_NODES * LATDIM];
__device__ int   g_cnt[N_NODES];       // zero-init; re-zeroed by scan each run
__device__ int   g_bsum[64];           // lookback slots: 0 = unpublished, else total+1
__device__ int   g_rowptr[N_NODES + 1];
__device__ int   g_fill[N_NODES];
__device__ int   g_adj[N_EDGES];

// ---- packed f32x2 helpers (FFMA2 path; base sm_103 PTX — no 'a' features) ----
__device__ __forceinline__ ull pack2(float lo, float hi) {
    ull r;
    asm("mov.b64 %0, {%1, %2};" : "=l"(r)
        : "r"(__float_as_uint(lo)), "r"(__float_as_uint(hi)));
    return r;
}
__device__ __forceinline__ void fma2(ull& d, ull a, ull b) {
    asm("fma.rn.f32x2 %0, %1, %2, %3;" : "=l"(d) : "l"(a), "l"(b), "l"(d));
}
__device__ __forceinline__ void unpack2(ull v, float& lo, float& hi) {
    unsigned ulo, uhi;
    asm("mov.b64 {%0, %1}, %2;" : "=r"(ulo), "=r"(uhi) : "l"(v));
    lo = __uint_as_float(ulo);
    hi = __uint_as_float(uhi);
}

// ============================================================
// Kernel 1: fused Q/K/V projection + edge histogram.
// grid = (ceil(N/128), 4): y<3 GEMM slices, y==3 histogram.
// GEMM mainloop is software-pipelined: chunk c+1's A-tile LDGs are
// issued BEFORE chunk c's compute, hiding DRAM/L2 latency under the
// ~1700 issue-cycles of FFMA2 work. Single smem buffer (33KB static).
// ============================================================
__global__ __launch_bounds__(256, 2)
void gemm3_hist_kernel(const float* __restrict__ E,
                       const float* __restrict__ qW,
                       const float* __restrict__ kW,
                       const float* __restrict__ vW,
                       const int* __restrict__ rows,
                       int N, int nE)
{
    // --- histogram slice: scheduled after GEMM blocks, fills the tail wave ---
    if (blockIdx.y == 3) {
        int stride = gridDim.x * blockDim.x;
        for (int e = blockIdx.x * blockDim.x + threadIdx.x; e < nE; e += stride)
            atomicAdd(&g_cnt[rows[e]], 1);
        return;
    }

    __shared__ float As[32][132];   // A tile transposed: As[k][row]
    __shared__ float Bs[32][128];   // W tile: Bs[k][col]

    const float* W   = (blockIdx.y == 0) ? qW : (blockIdx.y == 1 ? kW : vW);
    float*       Out = (blockIdx.y == 0) ? g_Q : (blockIdx.y == 1 ? g_K : g_V);

    const int row0 = blockIdx.x * 128;
    const int tid  = threadIdx.x;
    const int tr   = (tid >> 4) << 3;   // thread row base (0..120)
    const int tc   = (tid & 15) << 2;   // col blocks [tc,tc+4) and [tc+64,tc+68)
    const int kq   = (tid & 7) * 4;     // A-load k offset
    const int rb   = tid >> 3;          // A-load row base

    ull acc[8][4];
#pragma unroll
    for (int i = 0; i < 8; i++)
#pragma unroll
        for (int j = 0; j < 4; j++) acc[i][j] = 0ULL;

    // prefetch A chunk 0 into registers
    float4 aq[4];
#pragma unroll
    for (int rr = 0; rr < 4; rr++) {
        int grow = row0 + rb + rr * 32;
        aq[rr] = (grow < N)
            ? __ldg((const float4*)(E + (size_t)grow * LATDIM + kq))
            : make_float4(0.f, 0.f, 0.f, 0.f);
    }

    for (int c = 0; c < 4; c++) {
        const int kc = c * 32;
        __syncthreads();                // previous chunk's compute fully done

        // B chunk load + store (W is L2-resident after wave 1)
#pragma unroll
        for (int v = tid; v < 32 * 32; v += 256) {
            int k = v >> 5, c4 = v & 31;
            *(float4*)&Bs[k][c4 * 4] =
                __ldg((const float4*)(W + (size_t)(kc + k) * LATDIM) + c4);
        }
        // A chunk store from prefetched registers (transposed)
#pragma unroll
        for (int rr = 0; rr < 4; rr++) {
            int r = rb + rr * 32;
            As[kq + 0][r] = aq[rr].x;
            As[kq + 1][r] = aq[rr].y;
            As[kq + 2][r] = aq[rr].z;
            As[kq + 3][r] = aq[rr].w;
        }
        __syncthreads();

        // issue next chunk's A LDGs now — latency hides under compute below
        if (c < 3) {
#pragma unroll
            for (int rr = 0; rr < 4; rr++) {
                int grow = row0 + rb + rr * 32;
                aq[rr] = (grow < N)
                    ? __ldg((const float4*)(E + (size_t)grow * LATDIM + kc + 32 + kq))
                    : make_float4(0.f, 0.f, 0.f, 0.f);
            }
        }

#pragma unroll 8
        for (int k = 0; k < 32; k++) {
            float4 a0 = *(const float4*)&As[k][tr];        // broadcast
            float4 a1 = *(const float4*)&As[k][tr + 4];    // broadcast
            ulonglong2 bq0 = *(const ulonglong2*)&Bs[k][tc];       // contiguous
            ulonglong2 bq1 = *(const ulonglong2*)&Bs[k][tc + 64];  // contiguous
            ull bb[4] = {bq0.x, bq0.y, bq1.x, bq1.y};
            ull aa[8];
            aa[0] = pack2(a0.x, a0.x); aa[1] = pack2(a0.y, a0.y);
            aa[2] = pack2(a0.z, a0.z); aa[3] = pack2(a0.w, a0.w);
            aa[4] = pack2(a1.x, a1.x); aa[5] = pack2(a1.y, a1.y);
            aa[6] = pack2(a1.z, a1.z); aa[7] = pack2(a1.w, a1.w);
#pragma unroll
            for (int i = 0; i < 8; i++) {
                fma2(acc[i][0], aa[i], bb[0]);
                fma2(acc[i][1], aa[i], bb[1]);
                fma2(acc[i][2], aa[i], bb[2]);
                fma2(acc[i][3], aa[i], bb[3]);
            }
        }
    }

#pragma unroll
    for (int i = 0; i < 8; i++) {
        int grow = row0 + tr + i;
        if (grow < N) {
            float o[8];
#pragma unroll
            for (int j = 0; j < 4; j++) unpack2(acc[i][j], o[2 * j], o[2 * j + 1]);
            *(float4*)(Out + (size_t)grow * LATDIM + tc)      = make_float4(o[0], o[1], o[2], o[3]);
            *(float4*)(Out + (size_t)grow * LATDIM + tc + 64) = make_float4(o[4], o[5], o[6], o[7]);
        }
    }
}

// ============================================================
// Single-launch exclusive scan with inter-block lookback (49 blocks,
// all co-resident: 49 < 148 SMs, spin-wait deadlock-free).
// ============================================================
__global__ __launch_bounds__(1024)
void scan_fused(int n) {
    __shared__ int warp_sums[32];
    __shared__ int s_offset;
    const int tid  = threadIdx.x;
    const int lane = tid & 31;
    const int wid  = tid >> 5;
    const int bid  = blockIdx.x;
    const int i    = bid * 1024 + tid;

    int v = (i < n) ? g_cnt[i] : 0;

    int s = v;
#pragma unroll
    for (int o = 1; o < 32; o <<= 1) {
        int t = __shfl_up_sync(0xffffffffu, s, o);
        if (lane >= o) s += t;
    }
    if (lane == 31) warp_sums[wid] = s;
    __syncthreads();
    if (wid == 0) {
        int w = warp_sums[lane];
#pragma unroll
        for (int o = 1; o < 32; o <<= 1) {
            int t = __shfl_up_sync(0xffffffffu, w, o);
            if (lane >= o) w += t;
        }
        warp_sums[lane] = w;
    }
    __syncthreads();
    int incl = s + (wid > 0 ? warp_sums[wid - 1] : 0);

    if (tid == 1023) atomicExch(&g_bsum[bid], incl + 1);
    if (tid == 0) s_offset = 0;
    __syncthreads();

    if (tid < bid) {
        int pv;
        do { pv = atomicAdd(&g_bsum[tid], 0); } while (pv == 0);
        atomicAdd(&s_offset, pv - 1);
    }
    __syncthreads();

    int r = s_offset + incl - v;
    if (i < n) {
        g_rowptr[i] = r;
        g_fill[i]   = r;
        g_cnt[i]    = 0;           // re-zero for next call's fused histogram
    } else if (i == n) {
        g_rowptr[n] = r;
    }
}

__global__ void scatter_kernel(const int* __restrict__ rows,
                               const int* __restrict__ cols, int nE) {
    int e = blockIdx.x * blockDim.x + threadIdx.x;
    if (e < 64) g_bsum[e] = 0;     // reset lookback slots for next call
    if (e < nE) {
        int r = rows[e];
        int pos = atomicAdd(&g_fill[r], 1);
        g_adj[pos] = cols[e];
    }
}

// ============================================================
// Kernel 2: fused per-node attention. One warp per node, 2-edge unroll.
// ============================================================
__global__ void attn_kernel(float* __restrict__ out, int N) {
    int warp = (blockIdx.x * blockDim.x + threadIdx.x) >> 5;
    int lane = threadIdx.x & 31;
    if (warp >= N) return;

    const float4 q = __ldg((const float4*)(g_Q + (size_t)warp * LATDIM) + lane);
    int beg = g_rowptr[warp];
    int end = g_rowptr[warp + 1];

    float ax = 0.f, ay = 0.f, az = 0.f, aw = 0.f, denom = 0.f;

    int i = beg;
    for (; i + 2 <= end; i += 2) {
        int c0 = __ldg(g_adj + i);
        int c1 = __ldg(g_adj + i + 1);
        const float4 k0 = __ldg((const float4*)(g_K + (size_t)c0 * LATDIM) + lane);
        const float4 v0 = __ldg((const float4*)(g_V + (size_t)c0 * LATDIM) + lane);
        const float4 k1 = __ldg((const float4*)(g_K + (size_t)c1 * LATDIM) + lane);
        const float4 v1 = __ldg((const float4*)(g_V + (size_t)c1 * LATDIM) + lane);

        float p0 = q.x * k0.x + q.y * k0.y + q.z * k0.z + q.w * k0.w;
        float p1 = q.x * k1.x + q.y * k1.y + q.z * k1.z + q.w * k1.w;
        p0 += __shfl_xor_sync(0xffffffffu, p0, 1);
        p1 += __shfl_xor_sync(0xffffffffu, p1, 1);
        p0 += __shfl_xor_sync(0xffffffffu, p0, 2);
        p1 += __shfl_xor_sync(0xffffffffu, p1, 2);
        p0 += __shfl_xor_sync(0xffffffffu, p0, 4);
        p1 += __shfl_xor_sync(0xffffffffu, p1, 4);
        p0 = fminf(fmaxf(p0, -10.f), 10.f);
        p1 = fminf(fmaxf(p1, -10.f), 10.f);
        float e0 = __expf(p0);
        float e1 = __expf(p1);
        denom += e0 + e1;
        ax = fmaf(e0, v0.x, ax); ax = fmaf(e1, v1.x, ax);
        ay = fmaf(e0, v0.y, ay); ay = fmaf(e1, v1.y, ay);
        az = fmaf(e0, v0.z, az); az = fmaf(e1, v1.z, az);
        aw = fmaf(e0, v0.w, aw); aw = fmaf(e1, v1.w, aw);
    }
    if (i < end) {
        int c = __ldg(g_adj + i);
        const float4 k4 = __ldg((const float4*)(g_K + (size_t)c * LATDIM) + lane);
        const float4 v4 = __ldg((const float4*)(g_V + (size_t)c * LATDIM) + lane);
        float p = q.x * k4.x + q.y * k4.y + q.z * k4.z + q.w * k4.w;
        p += __shfl_xor_sync(0xffffffffu, p, 1);
        p += __shfl_xor_sync(0xffffffffu, p, 2);
        p += __shfl_xor_sync(0xffffffffu, p, 4);
        p = fminf(fmaxf(p, -10.f), 10.f);
        float e = __expf(p);
        denom += e;
        ax = fmaf(e, v4.x, ax);
        ay = fmaf(e, v4.y, ay);
        az = fmaf(e, v4.z, az);
        aw = fmaf(e, v4.w, aw);
    }

    float inv = 1.f / (denom + 1e-8f);
    float4 o = make_float4(ax * inv, ay * inv, az * inv, aw * inv);
    *((float4*)out + (size_t)warp * 32 + lane) = o;
}

// ============================================================
extern "C" void kernel_launch(void* const* d_in, const int* in_sizes, int n_in,
                              void* d_out, int out_size) {
    const float* E    = (const float*)d_in[0];
    const float* qW   = (const float*)d_in[1];
    const float* kW   = (const float*)d_in[2];
    const float* vW   = (const float*)d_in[3];
    const int*   rows = (const int*)d_in[4];
    const int*   cols = (const int*)d_in[5];

    int N  = in_sizes[0] / LATDIM;
    int Eg = in_sizes[4];

    int nb = (N + 1023) / 1024;   // 49 blocks — all co-resident

    dim3 gg((N + 127) / 128, 4);
    gemm3_hist_kernel<<<gg, 256>>>(E, qW, kW, vW, rows, N, Eg);   // 1
    scan_fused<<<nb, 1024>>>(N);                                  // 2
    scatter_kernel<<<(Eg + 255) / 256, 256>>>(rows, cols, Eg);    // 3
    attn_kernel<<<(N + 7) / 8, 256>>>((float*)d_out, N);          // 4 <- ncu slot
}